// round 1
// baseline (speedup 1.0000x reference)
#include <cuda_runtime.h>
#include <math.h>

#define NNODES 100000
#define RREL 3
#define EEDGES 500000
#define HHEADS 4
#define FFEAT 64
#define INFEAT 256
#define HF 256          // HHEADS * FFEAT
#define NEG_SLOPE 0.2f

// ---------------- scratch (device globals; no runtime allocation) ----------
__device__ float g_z[NNODES * HF];           // projection for current relation (102.4 MB)
__device__ float g_el[NNODES * HHEADS];
__device__ float g_er[NNODES * HHEADS];
__device__ float g_m[NNODES * HHEADS];
__device__ float g_den[NNODES * HHEADS];
__device__ float g_e[EEDGES * HHEADS];       // per-edge scores (8 MB)

// ---------------- helpers ----------------
__device__ __forceinline__ void atomicMaxFloat(float* addr, float value) {
    // standard signed/unsigned split; correct for mixed signs, init = -inf
    if (value >= 0.0f) {
        atomicMax((int*)addr, __float_as_int(value));
    } else {
        atomicMin((unsigned int*)addr, __float_as_uint(value));
    }
}

// ---------------- kernels ----------------
__global__ void k_zero_out(float* __restrict__ out) {
    int i = blockIdx.x * blockDim.x + threadIdx.x;
    if (i < NNODES * HF) out[i] = 0.0f;
}

__global__ void k_init_mden() {
    int i = blockIdx.x * blockDim.x + threadIdx.x;
    if (i < NNODES * HHEADS) {
        g_m[i] = -INFINITY;
        g_den[i] = 0.0f;
    }
}

// z = x @ W_r      x: [NNODES, 256] row-major, W: [256, 256] row-major
#define BM 64
#define BN 64
#define BK 16
__global__ void k_gemm(const float* __restrict__ x, const float* __restrict__ W) {
    __shared__ float As[BM][BK + 1];
    __shared__ float Bs[BK][BN + 1];

    const int bm = blockIdx.x * BM;
    const int bn = blockIdx.y * BN;
    const int tid = threadIdx.x;          // 256 threads
    const int tr = tid >> 4;              // 0..15
    const int tc = tid & 15;              // 0..15

    float acc[4][4] = {};

    for (int k0 = 0; k0 < INFEAT; k0 += BK) {
        // load A tile 64x16 (256 float4 loads)
        {
            int row = tid >> 2;           // 0..63
            int c4  = (tid & 3) << 2;     // 0,4,8,12
            int gr  = bm + row;
            float4 v = make_float4(0.f, 0.f, 0.f, 0.f);
            if (gr < NNODES) v = *(const float4*)&x[(long)gr * INFEAT + k0 + c4];
            As[row][c4 + 0] = v.x; As[row][c4 + 1] = v.y;
            As[row][c4 + 2] = v.z; As[row][c4 + 3] = v.w;
        }
        // load B tile 16x64
        {
            int row = tid >> 4;           // 0..15
            int c4  = (tid & 15) << 2;    // 0..60
            float4 v = *(const float4*)&W[(k0 + row) * HF + bn + c4];
            Bs[row][c4 + 0] = v.x; Bs[row][c4 + 1] = v.y;
            Bs[row][c4 + 2] = v.z; Bs[row][c4 + 3] = v.w;
        }
        __syncthreads();

        #pragma unroll
        for (int k = 0; k < BK; k++) {
            float a[4], b[4];
            #pragma unroll
            for (int i = 0; i < 4; i++) a[i] = As[tr * 4 + i][k];
            #pragma unroll
            for (int j = 0; j < 4; j++) b[j] = Bs[k][tc * 4 + j];
            #pragma unroll
            for (int i = 0; i < 4; i++)
                #pragma unroll
                for (int j = 0; j < 4; j++)
                    acc[i][j] = fmaf(a[i], b[j], acc[i][j]);
        }
        __syncthreads();
    }

    #pragma unroll
    for (int i = 0; i < 4; i++) {
        int gr = bm + tr * 4 + i;
        if (gr >= NNODES) break;
        #pragma unroll
        for (int j = 0; j < 4; j++) {
            g_z[(long)gr * HF + bn + tc * 4 + j] = acc[i][j];
        }
    }
}

// per-node attention logits: el[n,h] = sum_f z[n,h,f]*al[h,f], same for er
__global__ void k_elr(const float* __restrict__ al, const float* __restrict__ ar) {
    int i = blockIdx.x * blockDim.x + threadIdx.x;
    if (i >= NNODES * HHEADS) return;
    int n = i / HHEADS;
    int h = i % HHEADS;
    const float4* zp  = (const float4*)&g_z[(long)n * HF + h * FFEAT];
    const float4* alp = (const float4*)&al[h * FFEAT];
    const float4* arp = (const float4*)&ar[h * FFEAT];
    float sl = 0.f, sr = 0.f;
    #pragma unroll
    for (int q = 0; q < FFEAT / 4; q++) {
        float4 z = zp[q], a = alp[q], b = arp[q];
        sl += z.x * a.x + z.y * a.y + z.z * a.z + z.w * a.w;
        sr += z.x * b.x + z.y * b.y + z.z * b.z + z.w * b.w;
    }
    g_el[i] = sl;
    g_er[i] = sr;
}

// pass1: e = leaky_relu(el[src]+er[dst]); segment max via atomics
__global__ void k_edge1(const int* __restrict__ src, const int* __restrict__ dst) {
    int e = blockIdx.x * blockDim.x + threadIdx.x;
    if (e >= EEDGES) return;
    int s = src[e], d = dst[e];
    #pragma unroll
    for (int h = 0; h < HHEADS; h++) {
        float v = g_el[s * HHEADS + h] + g_er[d * HHEADS + h];
        v = (v > 0.f) ? v : NEG_SLOPE * v;
        g_e[e * HHEADS + h] = v;
        atomicMaxFloat(&g_m[d * HHEADS + h], v);
    }
}

// pass2: ee = exp(e - m[dst]); segment sum via atomics
__global__ void k_edge2(const int* __restrict__ dst) {
    int e = blockIdx.x * blockDim.x + threadIdx.x;
    if (e >= EEDGES) return;
    int d = dst[e];
    #pragma unroll
    for (int h = 0; h < HHEADS; h++) {
        float ee = expf(g_e[e * HHEADS + h] - g_m[d * HHEADS + h]);
        g_e[e * HHEADS + h] = ee;
        atomicAdd(&g_den[d * HHEADS + h], ee);
    }
}

// pass3: out[dst] += alpha * z[src]   (warp per edge, vector reductions)
__global__ void k_edge3(const int* __restrict__ src, const int* __restrict__ dst,
                        float* __restrict__ out) {
    int gid  = blockIdx.x * blockDim.x + threadIdx.x;
    int warp = gid >> 5;
    int lane = threadIdx.x & 31;
    if (warp >= EEDGES) return;
    int s = src[warp], d = dst[warp];
    int h = lane >> 3;   // 8 lanes per head (64 floats per head / 8 floats per lane)
    float alpha = g_e[warp * HHEADS + h] / g_den[d * HHEADS + h];

    const float4* zp = (const float4*)&g_z[(long)s * HF + lane * 8];
    float4 z0 = zp[0], z1 = zp[1];
    float4 v0 = make_float4(z0.x * alpha, z0.y * alpha, z0.z * alpha, z0.w * alpha);
    float4 v1 = make_float4(z1.x * alpha, z1.y * alpha, z1.z * alpha, z1.w * alpha);

    float* op = &out[(long)d * HF + lane * 8];
#if __CUDA_ARCH__ >= 900
    atomicAdd((float4*)op,       v0);
    atomicAdd((float4*)(op + 4), v1);
#else
    atomicAdd(op + 0, v0.x); atomicAdd(op + 1, v0.y);
    atomicAdd(op + 2, v0.z); atomicAdd(op + 3, v0.w);
    atomicAdd(op + 4, v1.x); atomicAdd(op + 5, v1.y);
    atomicAdd(op + 6, v1.z); atomicAdd(op + 7, v1.w);
#endif
}

// final: out = elu(acc + sum_r bias[r])
__global__ void k_elu(float* __restrict__ out, const float* __restrict__ bias) {
    int i = blockIdx.x * blockDim.x + threadIdx.x;
    if (i >= NNODES * HF) return;
    int c = i % HF;
    float b = bias[c] + bias[HF + c] + bias[2 * HF + c];
    float v = out[i] + b;
    out[i] = (v > 0.f) ? v : expm1f(v);
}

// ---------------- launch ----------------
extern "C" void kernel_launch(void* const* d_in, const int* in_sizes, int n_in,
                              void* d_out, int out_size) {
    const float* x      = (const float*)d_in[0];   // [N, 256]
    const float* W      = (const float*)d_in[1];   // [R, 256, 256]
    const float* attn_l = (const float*)d_in[2];   // [R, H, F]
    const float* attn_r = (const float*)d_in[3];   // [R, H, F]
    const float* bias   = (const float*)d_in[4];   // [R, H*F]
    const int*   src    = (const int*)d_in[5];     // [R, E]
    const int*   dst    = (const int*)d_in[6];     // [R, E]
    float* out = (float*)d_out;                    // [N, H*F]

    k_zero_out<<<(NNODES * HF + 255) / 256, 256>>>(out);

    for (int r = 0; r < RREL; r++) {
        dim3 gg((NNODES + BM - 1) / BM, HF / BN);
        k_gemm<<<gg, 256>>>(x, W + (long)r * INFEAT * HF);
        k_init_mden<<<(NNODES * HHEADS + 255) / 256, 256>>>();
        k_elr<<<(NNODES * HHEADS + 255) / 256, 256>>>(attn_l + r * HF, attn_r + r * HF);
        k_edge1<<<(EEDGES + 255) / 256, 256>>>(src + (long)r * EEDGES, dst + (long)r * EEDGES);
        k_edge2<<<(EEDGES + 255) / 256, 256>>>(dst + (long)r * EEDGES);
        k_edge3<<<((long)EEDGES * 32 + 255) / 256, 256>>>(src + (long)r * EEDGES,
                                                          dst + (long)r * EEDGES, out);
    }

    k_elu<<<(NNODES * HF + 255) / 256, 256>>>(out, bias);
}

// round 2
// speedup vs baseline: 1.2871x; 1.2871x over previous
#include <cuda_runtime.h>
#include <math.h>

#define NNODES 100000
#define RREL 3
#define EEDGES 500000
#define HHEADS 4
#define FFEAT 64
#define INFEAT 256
#define HF 256
#define HFTOT 768       // R * HF
#define NEG_SLOPE 0.2f

// ---------------- scratch (device globals; no runtime allocation) ----------
__device__ float g_z[(long)RREL * NNODES * HF];     // 307 MB
__device__ float g_el[RREL * NNODES * HHEADS];      // [r][n][h], float4 per node
__device__ float g_er[RREL * NNODES * HHEADS];
__device__ float g_den[RREL * NNODES * HHEADS];
__device__ float g_e[(long)RREL * EEDGES * HHEADS]; // 24 MB

// ---------------- init: zero out + den ----------------
__global__ void k_zero(float* __restrict__ out) {
    int i = blockIdx.x * blockDim.x + threadIdx.x;
    int stride = gridDim.x * blockDim.x;
    for (int j = i; j < NNODES * HF; j += stride) out[j] = 0.0f;
    for (int j = i; j < RREL * NNODES * HHEADS; j += stride) g_den[j] = 0.0f;
}

// ---------------- fused GEMM (all relations) + el/er epilogue --------------
#define GBM 128
#define GBN 128
#define GBK 16

__global__ void k_gemm(const float* __restrict__ x, const float* __restrict__ W,
                       const float* __restrict__ attn_l, const float* __restrict__ attn_r) {
    __shared__ float As[GBK][GBM];   // transposed: As[k][m]
    __shared__ float Bs[GBK][GBN];

    const int bm   = blockIdx.x * GBM;
    const int gcol = blockIdx.y * GBN;        // 0..767
    const int r    = gcol >> 8;               // relation
    const int bn   = gcol & 255;              // column within relation (0 or 128)
    const float* Wr = W + (long)r * INFEAT * HF;

    const int tid = threadIdx.x;              // 256 threads
    const int tr  = tid >> 4;                 // 0..15
    const int tc  = tid & 15;                 // 0..15

    float acc[8][8] = {};
    float4 aR[2], bR[2];

    // prefetch tile k0=0
    {
        #pragma unroll
        for (int q = 0; q < 2; q++) {
            int i = tid + q * 256;            // A float4 index 0..511
            int row = i >> 2, c4 = (i & 3) << 2;
            int gr = bm + row;
            aR[q] = make_float4(0.f, 0.f, 0.f, 0.f);
            if (gr < NNODES) aR[q] = *(const float4*)&x[(long)gr * INFEAT + c4];
            int j = tid + q * 256;            // B float4 index
            int brow = j >> 5, bc4 = (j & 31) << 2;
            bR[q] = *(const float4*)&Wr[brow * HF + bn + bc4];
        }
    }

    for (int k0 = 0; k0 < INFEAT; k0 += GBK) {
        // regs -> smem
        #pragma unroll
        for (int q = 0; q < 2; q++) {
            int i = tid + q * 256;
            int row = i >> 2, c4 = (i & 3) << 2;
            As[c4 + 0][row] = aR[q].x; As[c4 + 1][row] = aR[q].y;
            As[c4 + 2][row] = aR[q].z; As[c4 + 3][row] = aR[q].w;
            int brow = i >> 5, bc4 = (i & 31) << 2;
            *(float4*)&Bs[brow][bc4] = bR[q];
        }
        __syncthreads();

        // prefetch next tile
        if (k0 + GBK < INFEAT) {
            #pragma unroll
            for (int q = 0; q < 2; q++) {
                int i = tid + q * 256;
                int row = i >> 2, c4 = (i & 3) << 2;
                int gr = bm + row;
                aR[q] = make_float4(0.f, 0.f, 0.f, 0.f);
                if (gr < NNODES) aR[q] = *(const float4*)&x[(long)gr * INFEAT + k0 + GBK + c4];
                int brow = i >> 5, bc4 = (i & 31) << 2;
                bR[q] = *(const float4*)&Wr[(k0 + GBK + brow) * HF + bn + bc4];
            }
        }

        #pragma unroll
        for (int k = 0; k < GBK; k++) {
            float a[8], b[8];
            *(float4*)&a[0] = *(float4*)&As[k][tr * 8];
            *(float4*)&a[4] = *(float4*)&As[k][tr * 8 + 4];
            *(float4*)&b[0] = *(float4*)&Bs[k][tc * 8];
            *(float4*)&b[4] = *(float4*)&Bs[k][tc * 8 + 4];
            #pragma unroll
            for (int i = 0; i < 8; i++)
                #pragma unroll
                for (int j = 0; j < 8; j++)
                    acc[i][j] = fmaf(a[i], b[j], acc[i][j]);
        }
        __syncthreads();
    }

    // write C + fused el/er epilogue
    const int h = (bn >> 6) + (tc >> 3);          // global head for this thread's 8 cols
    float alv[8], arv[8];
    #pragma unroll
    for (int j = 0; j < 8; j++) {
        int col = h * FFEAT + ((tc & 7) * 8) + j; // within [H,F] of this relation
        alv[j] = attn_l[r * HF + col];
        arv[j] = attn_r[r * HF + col];
    }

    #pragma unroll
    for (int i = 0; i < 8; i++) {
        int gr = bm + tr * 8 + i;
        bool ok = (gr < NNODES);
        if (ok) {
            float* cp = &g_z[((long)r * NNODES + gr) * HF + bn + tc * 8];
            *(float4*)cp       = *(float4*)&acc[i][0];
            *(float4*)(cp + 4) = *(float4*)&acc[i][4];
        }
        float sl = 0.f, sr = 0.f;
        #pragma unroll
        for (int j = 0; j < 8; j++) {
            sl = fmaf(acc[i][j], alv[j], sl);
            sr = fmaf(acc[i][j], arv[j], sr);
        }
        // reduce across the 8 lanes owning this head (consecutive lanes)
        #pragma unroll
        for (int o = 4; o >= 1; o >>= 1) {
            sl += __shfl_down_sync(0xffffffffu, sl, o);
            sr += __shfl_down_sync(0xffffffffu, sr, o);
        }
        if (ok && (tc & 7) == 0) {
            g_el[((long)r * NNODES + gr) * HHEADS + h] = sl;
            g_er[((long)r * NNODES + gr) * HHEADS + h] = sr;
        }
    }
}

// ---------------- edge pass 1: e, exp(e), den (no max needed) --------------
__global__ void k_edge1(const int* __restrict__ src, const int* __restrict__ dst) {
    int e = blockIdx.x * blockDim.x + threadIdx.x;
    int r = blockIdx.y;
    if (e >= EEDGES) return;
    int s = src[(long)r * EEDGES + e];
    int d = dst[(long)r * EEDGES + e];
    float4 l  = *(const float4*)&g_el[((long)r * NNODES + s) * HHEADS];
    float4 rr = *(const float4*)&g_er[((long)r * NNODES + d) * HHEADS];
    float v0 = l.x + rr.x, v1 = l.y + rr.y, v2 = l.z + rr.z, v3 = l.w + rr.w;
    v0 = (v0 > 0.f) ? v0 : NEG_SLOPE * v0;
    v1 = (v1 > 0.f) ? v1 : NEG_SLOPE * v1;
    v2 = (v2 > 0.f) ? v2 : NEG_SLOPE * v2;
    v3 = (v3 > 0.f) ? v3 : NEG_SLOPE * v3;
    float4 ee = make_float4(expf(v0), expf(v1), expf(v2), expf(v3));
    *(float4*)&g_e[((long)r * EEDGES + e) * HHEADS] = ee;
    float* dp = &g_den[((long)r * NNODES + d) * HHEADS];
    atomicAdd(dp + 0, ee.x); atomicAdd(dp + 1, ee.y);
    atomicAdd(dp + 2, ee.z); atomicAdd(dp + 3, ee.w);
}

// ---------------- edge pass 2: out[dst] += alpha * z[src] ------------------
__global__ void k_edge3(const int* __restrict__ src, const int* __restrict__ dst,
                        float* __restrict__ out) {
    long gid = (long)blockIdx.x * blockDim.x + threadIdx.x;
    long warp = gid >> 5;
    int lane = threadIdx.x & 31;
    int r = blockIdx.y;
    if (warp >= EEDGES) return;
    int s = src[(long)r * EEDGES + warp];
    int d = dst[(long)r * EEDGES + warp];
    int h = lane >> 3;
    float alpha = g_e[((long)r * EEDGES + warp) * HHEADS + h] /
                  g_den[((long)r * NNODES + d) * HHEADS + h];

    const float4* zp = (const float4*)&g_z[((long)r * NNODES + s) * HF + lane * 8];
    float4 z0 = zp[0], z1 = zp[1];
    float4 v0 = make_float4(z0.x * alpha, z0.y * alpha, z0.z * alpha, z0.w * alpha);
    float4 v1 = make_float4(z1.x * alpha, z1.y * alpha, z1.z * alpha, z1.w * alpha);

    float* op = &out[(long)d * HF + lane * 8];
    atomicAdd((float4*)op,       v0);
    atomicAdd((float4*)(op + 4), v1);
}

// ---------------- final: elu(out + sum_r bias) ------------------------------
__global__ void k_elu(float* __restrict__ out, const float* __restrict__ bias) {
    int i = blockIdx.x * blockDim.x + threadIdx.x;
    if (i >= NNODES * HF) return;
    int c = i & 255;
    float b = bias[c] + bias[HF + c] + bias[2 * HF + c];
    float v = out[i] + b;
    out[i] = (v > 0.f) ? v : expm1f(v);
}

// ---------------- launch ----------------
extern "C" void kernel_launch(void* const* d_in, const int* in_sizes, int n_in,
                              void* d_out, int out_size) {
    const float* x      = (const float*)d_in[0];
    const float* W      = (const float*)d_in[1];
    const float* attn_l = (const float*)d_in[2];
    const float* attn_r = (const float*)d_in[3];
    const float* bias   = (const float*)d_in[4];
    const int*   src    = (const int*)d_in[5];
    const int*   dst    = (const int*)d_in[6];
    float* out = (float*)d_out;

    k_zero<<<1024, 256>>>(out);

    dim3 gg((NNODES + GBM - 1) / GBM, HFTOT / GBN);   // 782 x 6
    k_gemm<<<gg, 256>>>(x, W, attn_l, attn_r);

    dim3 ge((EEDGES + 255) / 256, RREL);
    k_edge1<<<ge, 256>>>(src, dst);

    dim3 ge3((int)(((long)EEDGES * 32 + 255) / 256), RREL);
    k_edge3<<<ge3, 256>>>(src, dst, out);

    k_elu<<<(NNODES * HF + 255) / 256, 256>>>(out, bias);
}

// round 3
// speedup vs baseline: 1.2876x; 1.0004x over previous
#include <cuda_runtime.h>
#include <math.h>

#define NNODES 100000
#define RREL 3
#define EEDGES 500000
#define HHEADS 4
#define FFEAT 64
#define INFEAT 256
#define HF 256
#define HFTOT 768       // R * HF
#define NEG_SLOPE 0.2f

// ---------------- scratch (device globals; no runtime allocation) ----------
__device__ float g_z[(long)RREL * NNODES * HF];     // 307 MB
__device__ float g_el[RREL * NNODES * HHEADS];      // [r][n][h], float4 per node
__device__ float g_er[RREL * NNODES * HHEADS];
__device__ float g_den[RREL * NNODES * HHEADS];
__device__ float g_e[(long)RREL * EEDGES * HHEADS]; // 24 MB

// ---------------- init: zero out + den ----------------
__global__ void k_zero(float* __restrict__ out) {
    int i = blockIdx.x * blockDim.x + threadIdx.x;
    int stride = gridDim.x * blockDim.x;
    for (int j = i; j < NNODES * HF; j += stride) out[j] = 0.0f;
    for (int j = i; j < RREL * NNODES * HHEADS; j += stride) g_den[j] = 0.0f;
}

// ---------------- fused GEMM (all relations) + el/er epilogue --------------
#define GBM 128
#define GBN 128
#define GBK 16

__global__ void k_gemm(const float* __restrict__ x, const float* __restrict__ W,
                       const float* __restrict__ attn_l, const float* __restrict__ attn_r) {
    __shared__ float As[GBK][GBM];   // transposed: As[k][m]
    __shared__ float Bs[GBK][GBN];

    const int bm   = blockIdx.x * GBM;
    const int gcol = blockIdx.y * GBN;        // 0..767
    const int r    = gcol >> 8;               // relation
    const int bn   = gcol & 255;              // column within relation (0 or 128)
    const float* Wr = W + (long)r * INFEAT * HF;

    const int tid = threadIdx.x;              // 256 threads
    const int tr  = tid >> 4;                 // 0..15
    const int tc  = tid & 15;                 // 0..15

    float acc[8][8] = {};
    float4 aR[2], bR[2];

    // prefetch tile k0=0
    {
        #pragma unroll
        for (int q = 0; q < 2; q++) {
            int i = tid + q * 256;            // A float4 index 0..511
            int row = i >> 2, c4 = (i & 3) << 2;
            int gr = bm + row;
            aR[q] = make_float4(0.f, 0.f, 0.f, 0.f);
            if (gr < NNODES) aR[q] = *(const float4*)&x[(long)gr * INFEAT + c4];
            int j = tid + q * 256;            // B float4 index
            int brow = j >> 5, bc4 = (j & 31) << 2;
            bR[q] = *(const float4*)&Wr[brow * HF + bn + bc4];
        }
    }

    for (int k0 = 0; k0 < INFEAT; k0 += GBK) {
        // regs -> smem
        #pragma unroll
        for (int q = 0; q < 2; q++) {
            int i = tid + q * 256;
            int row = i >> 2, c4 = (i & 3) << 2;
            As[c4 + 0][row] = aR[q].x; As[c4 + 1][row] = aR[q].y;
            As[c4 + 2][row] = aR[q].z; As[c4 + 3][row] = aR[q].w;
            int brow = i >> 5, bc4 = (i & 31) << 2;
            *(float4*)&Bs[brow][bc4] = bR[q];
        }
        __syncthreads();

        // prefetch next tile
        if (k0 + GBK < INFEAT) {
            #pragma unroll
            for (int q = 0; q < 2; q++) {
                int i = tid + q * 256;
                int row = i >> 2, c4 = (i & 3) << 2;
                int gr = bm + row;
                aR[q] = make_float4(0.f, 0.f, 0.f, 0.f);
                if (gr < NNODES) aR[q] = *(const float4*)&x[(long)gr * INFEAT + k0 + GBK + c4];
                int brow = i >> 5, bc4 = (i & 31) << 2;
                bR[q] = *(const float4*)&Wr[(k0 + GBK + brow) * HF + bn + bc4];
            }
        }

        #pragma unroll
        for (int k = 0; k < GBK; k++) {
            float a[8], b[8];
            *(float4*)&a[0] = *(float4*)&As[k][tr * 8];
            *(float4*)&a[4] = *(float4*)&As[k][tr * 8 + 4];
            *(float4*)&b[0] = *(float4*)&Bs[k][tc * 8];
            *(float4*)&b[4] = *(float4*)&Bs[k][tc * 8 + 4];
            #pragma unroll
            for (int i = 0; i < 8; i++)
                #pragma unroll
                for (int j = 0; j < 8; j++)
                    acc[i][j] = fmaf(a[i], b[j], acc[i][j]);
        }
        __syncthreads();
    }

    // write C + fused el/er epilogue
    const int h = (bn >> 6) + (tc >> 3);          // global head for this thread's 8 cols
    float alv[8], arv[8];
    #pragma unroll
    for (int j = 0; j < 8; j++) {
        int col = h * FFEAT + ((tc & 7) * 8) + j; // within [H,F] of this relation
        alv[j] = attn_l[r * HF + col];
        arv[j] = attn_r[r * HF + col];
    }

    #pragma unroll
    for (int i = 0; i < 8; i++) {
        int gr = bm + tr * 8 + i;
        bool ok = (gr < NNODES);
        if (ok) {
            float* cp = &g_z[((long)r * NNODES + gr) * HF + bn + tc * 8];
            *(float4*)cp       = *(float4*)&acc[i][0];
            *(float4*)(cp + 4) = *(float4*)&acc[i][4];
        }
        float sl = 0.f, sr = 0.f;
        #pragma unroll
        for (int j = 0; j < 8; j++) {
            sl = fmaf(acc[i][j], alv[j], sl);
            sr = fmaf(acc[i][j], arv[j], sr);
        }
        // reduce across the 8 lanes owning this head (consecutive lanes)
        #pragma unroll
        for (int o = 4; o >= 1; o >>= 1) {
            sl += __shfl_down_sync(0xffffffffu, sl, o);
            sr += __shfl_down_sync(0xffffffffu, sr, o);
        }
        if (ok && (tc & 7) == 0) {
            g_el[((long)r * NNODES + gr) * HHEADS + h] = sl;
            g_er[((long)r * NNODES + gr) * HHEADS + h] = sr;
        }
    }
}

// ---------------- edge pass 1: e, exp(e), den (no max needed) --------------
__global__ void k_edge1(const int* __restrict__ src, const int* __restrict__ dst) {
    int e = blockIdx.x * blockDim.x + threadIdx.x;
    int r = blockIdx.y;
    if (e >= EEDGES) return;
    int s = src[(long)r * EEDGES + e];
    int d = dst[(long)r * EEDGES + e];
    float4 l  = *(const float4*)&g_el[((long)r * NNODES + s) * HHEADS];
    float4 rr = *(const float4*)&g_er[((long)r * NNODES + d) * HHEADS];
    float v0 = l.x + rr.x, v1 = l.y + rr.y, v2 = l.z + rr.z, v3 = l.w + rr.w;
    v0 = (v0 > 0.f) ? v0 : NEG_SLOPE * v0;
    v1 = (v1 > 0.f) ? v1 : NEG_SLOPE * v1;
    v2 = (v2 > 0.f) ? v2 : NEG_SLOPE * v2;
    v3 = (v3 > 0.f) ? v3 : NEG_SLOPE * v3;
    float4 ee = make_float4(expf(v0), expf(v1), expf(v2), expf(v3));
    *(float4*)&g_e[((long)r * EEDGES + e) * HHEADS] = ee;
    float* dp = &g_den[((long)r * NNODES + d) * HHEADS];
    atomicAdd(dp + 0, ee.x); atomicAdd(dp + 1, ee.y);
    atomicAdd(dp + 2, ee.z); atomicAdd(dp + 3, ee.w);
}

// ---------------- edge pass 2: out[dst] += alpha * z[src] ------------------
__global__ void k_edge3(const int* __restrict__ src, const int* __restrict__ dst,
                        float* __restrict__ out) {
    long gid = (long)blockIdx.x * blockDim.x + threadIdx.x;
    long warp = gid >> 5;
    int lane = threadIdx.x & 31;
    int r = blockIdx.y;
    if (warp >= EEDGES) return;
    int s = src[(long)r * EEDGES + warp];
    int d = dst[(long)r * EEDGES + warp];
    int h = lane >> 3;
    float alpha = g_e[((long)r * EEDGES + warp) * HHEADS + h] /
                  g_den[((long)r * NNODES + d) * HHEADS + h];

    const float4* zp = (const float4*)&g_z[((long)r * NNODES + s) * HF + lane * 8];
    float4 z0 = zp[0], z1 = zp[1];
    float4 v0 = make_float4(z0.x * alpha, z0.y * alpha, z0.z * alpha, z0.w * alpha);
    float4 v1 = make_float4(z1.x * alpha, z1.y * alpha, z1.z * alpha, z1.w * alpha);

    float* op = &out[(long)d * HF + lane * 8];
    atomicAdd((float4*)op,       v0);
    atomicAdd((float4*)(op + 4), v1);
}

// ---------------- final: elu(out + sum_r bias) ------------------------------
__global__ void k_elu(float* __restrict__ out, const float* __restrict__ bias) {
    int i = blockIdx.x * blockDim.x + threadIdx.x;
    if (i >= NNODES * HF) return;
    int c = i & 255;
    float b = bias[c] + bias[HF + c] + bias[2 * HF + c];
    float v = out[i] + b;
    out[i] = (v > 0.f) ? v : expm1f(v);
}

// ---------------- launch ----------------
extern "C" void kernel_launch(void* const* d_in, const int* in_sizes, int n_in,
                              void* d_out, int out_size) {
    const float* x      = (const float*)d_in[0];
    const float* W      = (const float*)d_in[1];
    const float* attn_l = (const float*)d_in[2];
    const float* attn_r = (const float*)d_in[3];
    const float* bias   = (const float*)d_in[4];
    const int*   src    = (const int*)d_in[5];
    const int*   dst    = (const int*)d_in[6];
    float* out = (float*)d_out;

    k_zero<<<1024, 256>>>(out);

    dim3 gg((NNODES + GBM - 1) / GBM, HFTOT / GBN);   // 782 x 6
    k_gemm<<<gg, 256>>>(x, W, attn_l, attn_r);

    dim3 ge((EEDGES + 255) / 256, RREL);
    k_edge1<<<ge, 256>>>(src, dst);

    dim3 ge3((int)(((long)EEDGES * 32 + 255) / 256), RREL);
    k_edge3<<<ge3, 256>>>(src, dst, out);

    k_elu<<<(NNODES * HF + 255) / 256, 256>>>(out, bias);
}